// round 2
// baseline (speedup 1.0000x reference)
#include <cuda_runtime.h>
#include <math.h>

// ---------------- problem constants ----------------
#define BATCH   2
#define NTOK    5760
#define M_TOT   (BATCH * NTOK)   // 11520 tokens
#define DD      512              // model dim
#define HDIM    1960             // hidden dim
#define KTAPS   49               // 7x7
#define KH      7
#define CCH     40               // fold channels = 1960/49
#define HH      60
#define WWID    108
#define PAD     3
#define HP      66               // H + 2*PAD
#define WP      114              // W + 2*PAD
#define OHN     20               // (60+6-7)/3+1
#define OWN     36               // (108+6-7)/3+1
#define LLP     720              // OHN*OWN
#define BPF     16               // (b*n)/L
#define IMGPIX  (HP * WP)        // 7524
#define NIMG    (BPF * CCH)      // 640

// ---------------- scratch (static device globals; no allocations) ----------------
__device__ float g_h[(size_t)M_TOT * HDIM];           // 90.3 MB : x@W1+b1
__device__ float g_img[(size_t)NIMG * IMGPIX];        // 19.3 MB : folded+normalized padded images
__device__ float g_g[(size_t)M_TOT * HDIM];           // 90.3 MB : gelu(unfold(img))

// ---------------- generic fp32 SGEMM: C = A*B + bias ----------------
// Assumes: M % 128 == 0, K % 8 == 0, N % 4 == 0 (true for both GEMMs here).
// Block tile 128x128, BK=8, 256 threads, 8x8 per thread.
__global__ __launch_bounds__(256) void sgemm_bias(
    const float* __restrict__ A, const float* __restrict__ B,
    const float* __restrict__ bias, float* __restrict__ C,
    int M, int N, int K)
{
    const int BM = 128, BN = 128, BK = 8, TM = 8, TN = 8;
    __shared__ float As[BK][BM];
    __shared__ float Bs[BK][BN];

    const int tid  = threadIdx.x;
    const int row0 = blockIdx.y * BM;
    const int col0 = blockIdx.x * BN;

    // A-tile load map: thread -> (arow in [0,128), acol in {0,4}) as one float4
    const int arow = tid >> 1;
    const int acol = (tid & 1) << 2;
    // B-tile load map: thread -> (brow in [0,8), bcol in [0,128) step 4) as one float4
    const int brow = tid >> 5;
    const int bcol = (tid & 31) << 2;

    const int trow = (tid >> 4) * TM;   // 16x16 thread grid over the 128x128 tile
    const int tcol = (tid & 15) * TN;

    float acc[TM][TN];
#pragma unroll
    for (int i = 0; i < TM; i++)
#pragma unroll
        for (int j = 0; j < TN; j++) acc[i][j] = 0.f;

    const float* Aptr = A + (size_t)(row0 + arow) * K + acol;
    const int gcol = col0 + bcol;

    for (int k0 = 0; k0 < K; k0 += BK) {
        // load A (always in-bounds: M%128==0, K%8==0)
        float4 av = *reinterpret_cast<const float4*>(Aptr + k0);
        As[acol + 0][arow] = av.x;
        As[acol + 1][arow] = av.y;
        As[acol + 2][arow] = av.z;
        As[acol + 3][arow] = av.w;
        // load B (N-guard: gcol%4==0 && N%4==0 -> float4 fully in or out)
        float4 bv = make_float4(0.f, 0.f, 0.f, 0.f);
        if (gcol < N)
            bv = *reinterpret_cast<const float4*>(&B[(size_t)(k0 + brow) * N + gcol]);
        Bs[brow][bcol + 0] = bv.x;
        Bs[brow][bcol + 1] = bv.y;
        Bs[brow][bcol + 2] = bv.z;
        Bs[brow][bcol + 3] = bv.w;
        __syncthreads();

#pragma unroll
        for (int kk = 0; kk < BK; kk++) {
            float ar[TM], br[TN];
            // vectorized shared reads (trow, tcol are multiples of 8 -> 16B aligned)
            *reinterpret_cast<float4*>(&ar[0]) = *reinterpret_cast<const float4*>(&As[kk][trow]);
            *reinterpret_cast<float4*>(&ar[4]) = *reinterpret_cast<const float4*>(&As[kk][trow + 4]);
            *reinterpret_cast<float4*>(&br[0]) = *reinterpret_cast<const float4*>(&Bs[kk][tcol]);
            *reinterpret_cast<float4*>(&br[4]) = *reinterpret_cast<const float4*>(&Bs[kk][tcol + 4]);
#pragma unroll
            for (int i = 0; i < TM; i++)
#pragma unroll
                for (int j = 0; j < TN; j++)
                    acc[i][j] = fmaf(ar[i], br[j], acc[i][j]);
        }
        __syncthreads();
    }

    // epilogue: += bias, store (N-guard in float4 chunks)
#pragma unroll
    for (int i = 0; i < TM; i++) {
        const size_t row = (size_t)(row0 + trow + i);
#pragma unroll
        for (int j = 0; j < TN; j += 4) {
            const int col = col0 + tcol + j;
            if (col < N) {
                float4 v;
                v.x = acc[i][j + 0] + bias[col + 0];
                v.y = acc[i][j + 1] + bias[col + 1];
                v.z = acc[i][j + 2] + bias[col + 2];
                v.w = acc[i][j + 3] + bias[col + 3];
                *reinterpret_cast<float4*>(&C[row * (size_t)N + col]) = v;
            }
        }
    }
}

// ---------------- fold (gather form) + overlap-count normalize + crop/zero-pad ----------------
// img[bp, c, pi, pj] = (1/count) * sum over contributing (l, k) of h[bp*720+l, c*49+k]
// Zero outside the crop region [PAD, PAD+H) x [PAD, PAD+W) (matches fold-crop + zero re-pad).
__global__ void fold_kernel(const float* __restrict__ h, float* __restrict__ img)
{
    const int idx = blockIdx.x * blockDim.x + threadIdx.x;
    if (idx >= NIMG * IMGPIX) return;
    const int pix = idx % IMGPIX;
    const int bc  = idx / IMGPIX;
    const int c   = bc % CCH;
    const int bp  = bc / CCH;
    const int pi  = pix / WP;
    const int pj  = pix % WP;

    float out = 0.f;
    if (pi >= PAD && pi < PAD + HH && pj >= PAD && pj < PAD + WWID) {
        // contributing output-patch rows: ceil((pi-6)/3) <= oi <= floor(pi/3), clamped to [0, OHN)
        const int oi_lo = max(0, (pi - 4) / 3);     // == max(0, ceil((pi-6)/3)) for pi >= 3
        const int oi_hi = min(OHN - 1, pi / 3);
        const int oj_lo = max(0, (pj - 4) / 3);
        const int oj_hi = min(OWN - 1, pj / 3);

        float sum = 0.f;
        for (int oi = oi_lo; oi <= oi_hi; ++oi) {
            const int ki = pi - 3 * oi;
            for (int oj = oj_lo; oj <= oj_hi; ++oj) {
                const int kj = pj - 3 * oj;
                const int l = oi * OWN + oj;
                const int k = ki * KH + kj;
                sum += h[(size_t)(bp * LLP + l) * HDIM + c * KTAPS + k];
            }
        }
        const int cnt = (oi_hi - oi_lo + 1) * (oj_hi - oj_lo + 1);
        out = sum / (float)cnt;
    }
    img[idx] = out;
}

// ---------------- unfold + exact GELU ----------------
// g[token, c*49+k] = gelu( img[bp*40+c, (oi*3+ki)*WP + (oj*3+kj)] )
__global__ void unfold_gelu_kernel(const float* __restrict__ img, float* __restrict__ g)
{
    const int idx = blockIdx.x * blockDim.x + threadIdx.x;   // < 22,579,200 (fits int32)
    if (idx >= M_TOT * HDIM) return;
    const int j     = idx % HDIM;
    const int token = idx / HDIM;
    const int bp = token / LLP;
    const int l  = token % LLP;
    const int c  = j / KTAPS;
    const int k  = j % KTAPS;
    const int oi = l / OWN, oj = l % OWN;
    const int ki = k / KH,  kj = k % KH;
    const int pix = (oi * 3 + ki) * WP + (oj * 3 + kj);

    const float v = img[(size_t)(bp * CCH + c) * IMGPIX + pix];
    // exact GELU: 0.5*x*(1+erf(x/sqrt(2)))
    g[idx] = 0.5f * v * (1.f + erff(v * 0.7071067811865475f));
}

// ---------------- launch ----------------
extern "C" void kernel_launch(void* const* d_in, const int* in_sizes, int n_in,
                              void* d_out, int out_size)
{
    const float* x  = (const float*)d_in[0];   // (2, 5760, 512)
    const float* W1 = (const float*)d_in[1];   // (512, 1960)
    const float* b1 = (const float*)d_in[2];   // (1960,)
    const float* W2 = (const float*)d_in[3];   // (1960, 512)
    const float* b2 = (const float*)d_in[4];   // (512,)
    float* out = (float*)d_out;                // (2, 5760, 512)

    float *h_ptr, *img_ptr, *g_ptr;
    cudaGetSymbolAddress((void**)&h_ptr,   g_h);
    cudaGetSymbolAddress((void**)&img_ptr, g_img);
    cudaGetSymbolAddress((void**)&g_ptr,   g_g);

    // GEMM1: h = x @ W1 + b1   (11520 x 1960, K = 512)
    {
        dim3 grid((HDIM + 127) / 128, M_TOT / 128);   // (16, 90)
        sgemm_bias<<<grid, 256>>>(x, W1, b1, h_ptr, M_TOT, HDIM, DD);
    }
    // fold + normalize
    {
        const int total = NIMG * IMGPIX;              // 4,815,360
        fold_kernel<<<(total + 255) / 256, 256>>>(h_ptr, img_ptr);
    }
    // unfold + gelu
    {
        const int total = M_TOT * HDIM;               // 22,579,200
        unfold_gelu_kernel<<<(total + 255) / 256, 256>>>(img_ptr, g_ptr);
    }
    // GEMM2: out = g @ W2 + b2  (11520 x 512, K = 1960)
    {
        dim3 grid((DD + 127) / 128, M_TOT / 128);     // (4, 90)
        sgemm_bias<<<grid, 256>>>(g_ptr, W2, b2, out, M_TOT, DD, HDIM);
    }
}

// round 4
// speedup vs baseline: 2.3850x; 2.3850x over previous
#include <cuda_runtime.h>
#include <cuda_bf16.h>
#include <cstdint>
#include <math.h>

// ---------------- problem constants ----------------
#define BATCH   2
#define NTOK    5760
#define M_TOT   (BATCH * NTOK)   // 11520 tokens
#define DD      512              // model dim
#define HDIM    1960             // hidden dim
#define KTAPS   49               // 7x7
#define KH      7
#define CCH     40               // fold channels
#define HH      60
#define WWID    108
#define PAD     3
#define HP      66
#define WP      114
#define OHN     20
#define OWN     36
#define LLP     720
#define BPF     16
#define IMGPIX  (HP * WP)        // 7524
#define NIMG    (BPF * CCH)      // 640

// K-expanded (3x split) sizes
#define KC1     (3 * DD)         // 1536
#define KC2     5888             // 3*1960=5880 padded to 184*32
#define NPAD1   2048             // 1960 padded to 16*128
#define NPAD2   512

// ---------------- scratch (static device globals; no allocations) ----------------
__device__ __nv_bfloat16 g_Aexp[(size_t)M_TOT * KC2];   // 135.7 MB (reused by both GEMMs)
__device__ __nv_bfloat16 g_Bexp[(size_t)NPAD1 * KC1];   // 6.3 MB (>= 512*5888)
__device__ float g_h[(size_t)M_TOT * HDIM];             // 90 MB
__device__ float g_img[(size_t)NIMG * IMGPIX];          // 19 MB

// ============================================================================
// helpers
// ============================================================================
__device__ __forceinline__ uint32_t smem_to_u32(const void* p) {
    uint32_t a;
    asm("{ .reg .u64 t; cvta.to.shared.u64 t, %1; cvt.u32.u64 %0, t; }" : "=r"(a) : "l"(p));
    return a;
}
__device__ __forceinline__ void cp16(uint32_t s, const void* g) {
    asm volatile("cp.async.cg.shared.global [%0], [%1], 16;" :: "r"(s), "l"(g));
}
#define CP_COMMIT() asm volatile("cp.async.commit_group;" ::: "memory")
#define CP_WAIT1()  asm volatile("cp.async.wait_group 1;" ::: "memory")

__device__ __forceinline__ void ldm_x4(uint32_t& r0, uint32_t& r1, uint32_t& r2, uint32_t& r3,
                                       uint32_t addr) {
    asm volatile("ldmatrix.sync.aligned.m8n8.x4.shared.b16 {%0,%1,%2,%3}, [%4];"
                 : "=r"(r0), "=r"(r1), "=r"(r2), "=r"(r3) : "r"(addr));
}
__device__ __forceinline__ void ldm_x2(uint32_t& r0, uint32_t& r1, uint32_t addr) {
    asm volatile("ldmatrix.sync.aligned.m8n8.x2.shared.b16 {%0,%1}, [%2];"
                 : "=r"(r0), "=r"(r1) : "r"(addr));
}
__device__ __forceinline__ void mma_16816(float& c0, float& c1, float& c2, float& c3,
                                          uint32_t a0, uint32_t a1, uint32_t a2, uint32_t a3,
                                          uint32_t b0, uint32_t b1) {
    asm volatile("mma.sync.aligned.m16n8k16.row.col.f32.bf16.bf16.f32 "
                 "{%0,%1,%2,%3}, {%4,%5,%6,%7}, {%8,%9}, {%0,%1,%2,%3};"
                 : "+f"(c0), "+f"(c1), "+f"(c2), "+f"(c3)
                 : "r"(a0), "r"(a1), "r"(a2), "r"(a3), "r"(b0), "r"(b1));
}

// ============================================================================
// HMMA bf16 GEMM: C[M x N] = A[M x Kc] @ B^T + bias (B stored [Npad x Kc], K-major)
// 128x128 CTA tile, BK=32, 256 threads (8 warps: 2m x 4n, 64x32 warp tiles),
// cp.async double buffer, 80B-padded SMEM rows (conflict-free ldmatrix).
// Requires: M%128==0, Npad%128==0, Kc%32==0. Stores guarded by col<N.
// ============================================================================
#define ROWB 80u                 // padded row bytes (64B data + 16B pad)
#define TILE_B (128u * ROWB)     // 10240 B per tile

__global__ __launch_bounds__(256)
void hmma_gemm(const __nv_bfloat16* __restrict__ A, const __nv_bfloat16* __restrict__ B,
               const float* __restrict__ bias, float* __restrict__ C, int Kc, int N)
{
    __shared__ __align__(16) char smem[4 * TILE_B];     // [bufA0|bufA1|bufB0|bufB1]
    const uint32_t sbase = smem_to_u32(smem);
    const uint32_t sA[2] = { sbase,              sbase + TILE_B };
    const uint32_t sB[2] = { sbase + 2 * TILE_B, sbase + 3 * TILE_B };

    const int tid  = threadIdx.x;
    const int wid  = tid >> 5;
    const int lane = tid & 31;
    const int row0 = blockIdx.y * 128;
    const int col0 = blockIdx.x * 128;

    const int wm = wid & 1;       // 0..1  -> m offset wm*64
    const int wn = wid >> 1;      // 0..3  -> n offset wn*32

    // loader mapping: 256 threads cover 64 rows x 4 chunks of 16B per pass
    const int lrow = tid >> 2;    // 0..63
    const int lch  = tid & 3;     // 16B chunk in 64B row

    float acc[4][4][4];
#pragma unroll
    for (int mi = 0; mi < 4; mi++)
#pragma unroll
        for (int ni = 0; ni < 4; ni++)
#pragma unroll
            for (int r = 0; r < 4; r++) acc[mi][ni][r] = 0.f;

    const int nk = Kc >> 5;       // BK=32 stages

    // ---- prologue: stage 0 ----
    {
        const int k0 = 0;
#pragma unroll
        for (int rr = 0; rr < 128; rr += 64) {
            cp16(sA[0] + (lrow + rr) * ROWB + lch * 16,
                 A + (size_t)(row0 + lrow + rr) * Kc + k0 + lch * 8);
            cp16(sB[0] + (lrow + rr) * ROWB + lch * 16,
                 B + (size_t)(col0 + lrow + rr) * Kc + k0 + lch * 8);
        }
    }
    CP_COMMIT();

    for (int i = 0; i < nk; i++) {
        if (i + 1 < nk) {
            const int k0 = (i + 1) << 5;
            const int b = (i + 1) & 1;
#pragma unroll
            for (int rr = 0; rr < 128; rr += 64) {
                cp16(sA[b] + (lrow + rr) * ROWB + lch * 16,
                     A + (size_t)(row0 + lrow + rr) * Kc + k0 + lch * 8);
                cp16(sB[b] + (lrow + rr) * ROWB + lch * 16,
                     B + (size_t)(col0 + lrow + rr) * Kc + k0 + lch * 8);
            }
        }
        CP_COMMIT();
        CP_WAIT1();
        __syncthreads();

        const int b = i & 1;
        const uint32_t aBase = sA[b] + (uint32_t)((wm * 64 + (lane & 15)) * ROWB + ((lane >> 4) << 4));
        const uint32_t bBase = sB[b] + (uint32_t)((wn * 32 + (lane & 7)) * ROWB + (((lane >> 3) & 1) << 4));

#pragma unroll
        for (int ks = 0; ks < 2; ks++) {
            uint32_t af[4][4];
#pragma unroll
            for (int mi = 0; mi < 4; mi++)
                ldm_x4(af[mi][0], af[mi][1], af[mi][2], af[mi][3],
                       aBase + (uint32_t)(mi * 16 * ROWB + ks * 32));
            uint32_t bf[4][2];
#pragma unroll
            for (int ni = 0; ni < 4; ni++)
                ldm_x2(bf[ni][0], bf[ni][1],
                       bBase + (uint32_t)(ni * 8 * ROWB + ks * 32));
#pragma unroll
            for (int mi = 0; mi < 4; mi++)
#pragma unroll
                for (int ni = 0; ni < 4; ni++)
                    mma_16816(acc[mi][ni][0], acc[mi][ni][1], acc[mi][ni][2], acc[mi][ni][3],
                              af[mi][0], af[mi][1], af[mi][2], af[mi][3],
                              bf[ni][0], bf[ni][1]);
        }
        __syncthreads();
    }

    // ---- epilogue ----
    const int g = lane >> 2, t = lane & 3;
#pragma unroll
    for (int mi = 0; mi < 4; mi++) {
        const int row = row0 + wm * 64 + mi * 16 + g;
#pragma unroll
        for (int ni = 0; ni < 4; ni++) {
            const int col = col0 + wn * 32 + ni * 8 + 2 * t;
            if (col < N) {
                const float bc0 = bias[col], bc1 = bias[col + 1];
                float2 v0 = make_float2(acc[mi][ni][0] + bc0, acc[mi][ni][1] + bc1);
                float2 v1 = make_float2(acc[mi][ni][2] + bc0, acc[mi][ni][3] + bc1);
                *reinterpret_cast<float2*>(&C[(size_t)row * N + col]) = v0;
                *reinterpret_cast<float2*>(&C[(size_t)(row + 8) * N + col]) = v1;
            }
        }
    }
}

// ============================================================================
// bf16 split helpers + expansion kernels
// ============================================================================
__device__ __forceinline__ void split_bf16(float v, __nv_bfloat16& hi, __nv_bfloat16& lo) {
    hi = __float2bfloat16(v);
    lo = __float2bfloat16(v - __bfloat162float(hi));
}

// x (M_TOT x 512 fp32) -> Aexp (M_TOT x 1536 bf16), layout [hi | lo | hi]
__global__ void expand_x_kernel(const float* __restrict__ x, __nv_bfloat16* __restrict__ Aexp)
{
    const int idx = blockIdx.x * blockDim.x + threadIdx.x;
    if (idx >= M_TOT * DD) return;
    const int m = idx / DD, k = idx % DD;
    __nv_bfloat16 hi, lo;
    split_bf16(x[idx], hi, lo);
    const size_t base = (size_t)m * KC1;
    Aexp[base + k] = hi;
    Aexp[base + DD + k] = lo;
    Aexp[base + 2 * DD + k] = hi;
}

// W (K x N fp32, row-major) -> Bexp (Npad x K3pad bf16, K-major), layout [hi | hi | lo]
__global__ void expand_W_kernel(const float* __restrict__ W, __nv_bfloat16* __restrict__ Bexp,
                                int K, int N, int Npad, int K3pad)
{
    const int idx = blockIdx.x * blockDim.x + threadIdx.x;
    if (idx >= Npad * K3pad) return;
    const int n = idx / K3pad, k3 = idx % K3pad;
    __nv_bfloat16 outv = __float2bfloat16(0.f);
    if (n < N && k3 < 3 * K) {
        const int r = k3 / K, k = k3 - r * K;
        __nv_bfloat16 hi, lo;
        split_bf16(W[(size_t)k * N + n], hi, lo);
        outv = (r < 2) ? hi : lo;
    }
    Bexp[idx] = outv;
}

// ---------------- fold (gather) + normalize + crop/zero-pad ----------------
__global__ void fold_kernel(const float* __restrict__ h, float* __restrict__ img)
{
    const int idx = blockIdx.x * blockDim.x + threadIdx.x;
    if (idx >= NIMG * IMGPIX) return;
    const int pix = idx % IMGPIX;
    const int bc  = idx / IMGPIX;
    const int c   = bc % CCH;
    const int bp  = bc / CCH;
    const int pi  = pix / WP;
    const int pj  = pix % WP;

    float out = 0.f;
    if (pi >= PAD && pi < PAD + HH && pj >= PAD && pj < PAD + WWID) {
        const int oi_lo = max(0, (pi - 4) / 3);
        const int oi_hi = min(OHN - 1, pi / 3);
        const int oj_lo = max(0, (pj - 4) / 3);
        const int oj_hi = min(OWN - 1, pj / 3);
        float sum = 0.f;
        for (int oi = oi_lo; oi <= oi_hi; ++oi) {
            const int ki = pi - 3 * oi;
            for (int oj = oj_lo; oj <= oj_hi; ++oj) {
                const int kj = pj - 3 * oj;
                sum += h[(size_t)(bp * LLP + oi * OWN + oj) * HDIM + c * KTAPS + ki * KH + kj];
            }
        }
        const int cnt = (oi_hi - oi_lo + 1) * (oj_hi - oj_lo + 1);
        out = sum / (float)cnt;
    }
    img[idx] = out;
}

// ---------------- unfold + exact GELU + bf16-split expansion ----------------
// Writes Aexp (M_TOT x 5888), layout [hi(0:1960) | lo | hi | zeros(5880:5888)]
__global__ void unfold_gelu_expand_kernel(const float* __restrict__ img,
                                          __nv_bfloat16* __restrict__ Aexp)
{
    const int idx = blockIdx.x * blockDim.x + threadIdx.x;
    if (idx >= M_TOT * HDIM) return;
    const int j     = idx % HDIM;
    const int token = idx / HDIM;
    const int bp = token / LLP;
    const int l  = token % LLP;
    const int c  = j / KTAPS;
    const int k  = j % KTAPS;
    const int oi = l / OWN, oj = l % OWN;
    const int ki = k / KH,  kj = k % KH;
    const int pix = (oi * 3 + ki) * WP + (oj * 3 + kj);

    const float v = img[(size_t)(bp * CCH + c) * IMGPIX + pix];
    const float ge = 0.5f * v * (1.f + erff(v * 0.7071067811865475f));

    __nv_bfloat16 hi, lo;
    split_bf16(ge, hi, lo);
    const size_t base = (size_t)token * KC2;
    Aexp[base + j] = hi;
    Aexp[base + HDIM + j] = lo;
    Aexp[base + 2 * HDIM + j] = hi;
    if (j < KC2 - 3 * HDIM)                 // zero the K padding (8 cols)
        Aexp[base + 3 * HDIM + j] = __float2bfloat16(0.f);
}

// ---------------- launch ----------------
extern "C" void kernel_launch(void* const* d_in, const int* in_sizes, int n_in,
                              void* d_out, int out_size)
{
    const float* x  = (const float*)d_in[0];   // (2, 5760, 512)
    const float* W1 = (const float*)d_in[1];   // (512, 1960)
    const float* b1 = (const float*)d_in[2];   // (1960,)
    const float* W2 = (const float*)d_in[3];   // (1960, 512)
    const float* b2 = (const float*)d_in[4];   // (512,)
    float* out = (float*)d_out;                // (2, 5760, 512)

    __nv_bfloat16 *Aexp, *Bexp;
    float *h_ptr, *img_ptr;
    cudaGetSymbolAddress((void**)&Aexp,    g_Aexp);
    cudaGetSymbolAddress((void**)&Bexp,    g_Bexp);
    cudaGetSymbolAddress((void**)&h_ptr,   g_h);
    cudaGetSymbolAddress((void**)&img_ptr, g_img);

    // --- GEMM1: h = x @ W1 + b1  (3x bf16 split on tensor cores) ---
    {
        int n = M_TOT * DD;
        expand_x_kernel<<<(n + 255) / 256, 256>>>(x, Aexp);
        int nb = NPAD1 * KC1;
        expand_W_kernel<<<(nb + 255) / 256, 256>>>(W1, Bexp, DD, HDIM, NPAD1, KC1);
        dim3 grid(NPAD1 / 128, M_TOT / 128);   // (16, 90)
        hmma_gemm<<<grid, 256>>>(Aexp, Bexp, b1, h_ptr, KC1, HDIM);
    }
    // --- fold + normalize ---
    {
        const int total = NIMG * IMGPIX;
        fold_kernel<<<(total + 255) / 256, 256>>>(h_ptr, img_ptr);
    }
    // --- unfold + gelu + expansion (Aexp reused) ---
    {
        const int total = M_TOT * HDIM;
        unfold_gelu_expand_kernel<<<(total + 255) / 256, 256>>>(img_ptr, Aexp);
        int nb = NPAD2 * KC2;
        expand_W_kernel<<<(nb + 255) / 256, 256>>>(W2, Bexp, HDIM, DD, NPAD2, KC2);
    }
    // --- GEMM2: out = g @ W2 + b2 ---
    {
        dim3 grid(NPAD2 / 128, M_TOT / 128);   // (4, 90)
        hmma_gemm<<<grid, 256>>>(Aexp, Bexp, b2, out, KC2, DD);
    }
}

// round 5
// speedup vs baseline: 2.6802x; 1.1238x over previous
#include <cuda_runtime.h>
#include <cuda_bf16.h>
#include <cstdint>
#include <math.h>

// ---------------- problem constants ----------------
#define BATCH   2
#define NTOK    5760
#define M_TOT   (BATCH * NTOK)   // 11520 tokens
#define DD      512              // model dim
#define HDIM    1960             // hidden dim
#define KTAPS   49               // 7x7
#define KH      7
#define CCH     40               // fold channels
#define HH      60
#define WWID    108
#define PAD     3
#define HP      66
#define WP      114
#define OHN     20
#define OWN     36
#define LLP     720
#define BPF     16
#define IMGPIX  (HP * WP)        // 7524
#define NIMG    (BPF * CCH)      // 640

// K-expanded (3x split) sizes
#define KC1     (3 * DD)         // 1536
#define KC2     5888             // 3*1960=5880 padded to 184*32
#define NPAD1   2048             // 1960 padded to 16*128
#define NPAD2   512

// ---------------- scratch (static device globals; no allocations) ----------------
__device__ __nv_bfloat16 g_Aexp[(size_t)M_TOT * KC2];   // 135.7 MB (reused by both GEMMs)
__device__ __nv_bfloat16 g_Bexp[(size_t)NPAD1 * KC1];   // 6.3 MB (>= 512*5888)
__device__ float g_h[(size_t)M_TOT * HDIM];             // 90 MB
__device__ float g_img[(size_t)NIMG * IMGPIX];          // 19 MB

// ============================================================================
// helpers
// ============================================================================
__device__ __forceinline__ uint32_t smem_to_u32(const void* p) {
    uint32_t a;
    asm("{ .reg .u64 t; cvta.to.shared.u64 t, %1; cvt.u32.u64 %0, t; }" : "=r"(a) : "l"(p));
    return a;
}
__device__ __forceinline__ void cp16(uint32_t s, const void* g) {
    asm volatile("cp.async.cg.shared.global [%0], [%1], 16;" :: "r"(s), "l"(g));
}
#define CP_COMMIT() asm volatile("cp.async.commit_group;" ::: "memory")
#define CP_WAIT2()  asm volatile("cp.async.wait_group 2;" ::: "memory")

__device__ __forceinline__ void ldm_x4(uint32_t& r0, uint32_t& r1, uint32_t& r2, uint32_t& r3,
                                       uint32_t addr) {
    asm volatile("ldmatrix.sync.aligned.m8n8.x4.shared.b16 {%0,%1,%2,%3}, [%4];"
                 : "=r"(r0), "=r"(r1), "=r"(r2), "=r"(r3) : "r"(addr));
}
__device__ __forceinline__ void ldm_x2(uint32_t& r0, uint32_t& r1, uint32_t addr) {
    asm volatile("ldmatrix.sync.aligned.m8n8.x2.shared.b16 {%0,%1}, [%2];"
                 : "=r"(r0), "=r"(r1) : "r"(addr));
}
__device__ __forceinline__ void mma_16816(float& c0, float& c1, float& c2, float& c3,
                                          uint32_t a0, uint32_t a1, uint32_t a2, uint32_t a3,
                                          uint32_t b0, uint32_t b1) {
    asm volatile("mma.sync.aligned.m16n8k16.row.col.f32.bf16.bf16.f32 "
                 "{%0,%1,%2,%3}, {%4,%5,%6,%7}, {%8,%9}, {%0,%1,%2,%3};"
                 : "+f"(c0), "+f"(c1), "+f"(c2), "+f"(c3)
                 : "r"(a0), "r"(a1), "r"(a2), "r"(a3), "r"(b0), "r"(b1));
}

// ============================================================================
// HMMA bf16 GEMM: C[M x N] = A[M x Kc] @ B^T + bias (B stored [Npad x Kc], K-major)
// 128x128 CTA tile, BK=32, 256 threads (8 warps: 2m x 4n, 64x32 warp tiles).
// 4-stage cp.async pipeline, one __syncthreads per stage, 80B-padded SMEM rows.
// Requires: M%128==0, Npad%128==0, Kc%32==0. Stores guarded by col<N.
// ============================================================================
#define ROWB   80u               // padded row bytes (64B data + 16B pad)
#define HTILE  (128u * ROWB)     // 10240 B (one operand, one stage)
#define STG_B  (2u * HTILE)      // 20480 B per stage (A + B)
#define STAGES 4
#define GEMM_SMEM (STAGES * STG_B)   // 81920 B

__global__ __launch_bounds__(256, 2)
void hmma_gemm(const __nv_bfloat16* __restrict__ A, const __nv_bfloat16* __restrict__ B,
               const float* __restrict__ bias, float* __restrict__ C, int Kc, int N)
{
    extern __shared__ __align__(16) char smem[];
    const uint32_t sbase = smem_to_u32(smem);

    const int tid  = threadIdx.x;
    const int wid  = tid >> 5;
    const int lane = tid & 31;
    const int row0 = blockIdx.y * 128;
    const int col0 = blockIdx.x * 128;

    const int wm = wid & 1;       // m offset wm*64
    const int wn = wid >> 1;      // n offset wn*32

    // loader mapping: 256 threads cover 64 rows x 4 chunks of 16B per pass
    const int lrow = tid >> 2;    // 0..63
    const int lch  = tid & 3;     // 16B chunk in 64B row
    const __nv_bfloat16* Ag = A + (size_t)(row0 + lrow) * Kc + lch * 8;
    const __nv_bfloat16* Bg = B + (size_t)(col0 + lrow) * Kc + lch * 8;
    const size_t strideA = (size_t)64 * Kc;

    float acc[4][4][4];
#pragma unroll
    for (int mi = 0; mi < 4; mi++)
#pragma unroll
        for (int ni = 0; ni < 4; ni++)
#pragma unroll
            for (int r = 0; r < 4; r++) acc[mi][ni][r] = 0.f;

    const int nk = Kc >> 5;       // BK=32 stages

    // ---- prologue: issue stages 0..STAGES-2, one commit group each ----
#pragma unroll
    for (int s = 0; s < STAGES - 1; s++) {
        const uint32_t sA = sbase + s * STG_B;
        const uint32_t sB = sA + HTILE;
        const int k0 = s << 5;
#pragma unroll
        for (int rr = 0; rr < 128; rr += 64) {
            cp16(sA + (lrow + rr) * ROWB + lch * 16, Ag + rr * (size_t)Kc + k0);
            cp16(sB + (lrow + rr) * ROWB + lch * 16, Bg + rr * (size_t)Kc + k0);
        }
        CP_COMMIT();
    }

    for (int i = 0; i < nk; i++) {
        CP_WAIT2();               // stage i arrived
        __syncthreads();          // all warps done with buffer (i+STAGES-1)%STAGES

        // issue stage i+STAGES-1 into the buffer freed at iteration i-1
        {
            const int s = i + STAGES - 1;
            if (s < nk) {
                const uint32_t sA = sbase + (s & (STAGES - 1)) * STG_B;
                const uint32_t sB = sA + HTILE;
                const int k0 = s << 5;
#pragma unroll
                for (int rr = 0; rr < 128; rr += 64) {
                    cp16(sA + (lrow + rr) * ROWB + lch * 16, Ag + rr * (size_t)Kc + k0);
                    cp16(sB + (lrow + rr) * ROWB + lch * 16, Bg + rr * (size_t)Kc + k0);
                }
            }
            CP_COMMIT();          // commit even when empty to keep group counting uniform
        }

        const uint32_t sA = sbase + (i & (STAGES - 1)) * STG_B;
        const uint32_t sB = sA + HTILE;
        const uint32_t aBase = sA + (uint32_t)((wm * 64 + (lane & 15)) * ROWB + ((lane >> 4) << 4));
        const uint32_t bBase = sB + (uint32_t)((wn * 32 + (lane & 7)) * ROWB + (((lane >> 3) & 1) << 4));

#pragma unroll
        for (int ks = 0; ks < 2; ks++) {
            uint32_t af[4][4];
#pragma unroll
            for (int mi = 0; mi < 4; mi++)
                ldm_x4(af[mi][0], af[mi][1], af[mi][2], af[mi][3],
                       aBase + (uint32_t)(mi * 16 * ROWB + ks * 32));
            uint32_t bf[4][2];
#pragma unroll
            for (int ni = 0; ni < 4; ni++)
                ldm_x2(bf[ni][0], bf[ni][1],
                       bBase + (uint32_t)(ni * 8 * ROWB + ks * 32));
#pragma unroll
            for (int mi = 0; mi < 4; mi++)
#pragma unroll
                for (int ni = 0; ni < 4; ni++)
                    mma_16816(acc[mi][ni][0], acc[mi][ni][1], acc[mi][ni][2], acc[mi][ni][3],
                              af[mi][0], af[mi][1], af[mi][2], af[mi][3],
                              bf[ni][0], bf[ni][1]);
        }
    }

    // ---- epilogue ----
    const int g = lane >> 2, t = lane & 3;
#pragma unroll
    for (int mi = 0; mi < 4; mi++) {
        const int row = row0 + wm * 64 + mi * 16 + g;
#pragma unroll
        for (int ni = 0; ni < 4; ni++) {
            const int col = col0 + wn * 32 + ni * 8 + 2 * t;
            if (col < N) {
                const float bc0 = bias[col], bc1 = bias[col + 1];
                float2 v0 = make_float2(acc[mi][ni][0] + bc0, acc[mi][ni][1] + bc1);
                float2 v1 = make_float2(acc[mi][ni][2] + bc0, acc[mi][ni][3] + bc1);
                *reinterpret_cast<float2*>(&C[(size_t)row * N + col]) = v0;
                *reinterpret_cast<float2*>(&C[(size_t)(row + 8) * N + col]) = v1;
            }
        }
    }
}

// ============================================================================
// bf16 split helpers + expansion kernels
// ============================================================================
__device__ __forceinline__ void split_bf16(float v, __nv_bfloat16& hi, __nv_bfloat16& lo) {
    hi = __float2bfloat16(v);
    lo = __float2bfloat16(v - __bfloat162float(hi));
}

// x (M_TOT x 512 fp32) -> Aexp (M_TOT x 1536 bf16), layout [hi | lo | hi]; paired stores
__global__ void expand_x_kernel(const float* __restrict__ x, __nv_bfloat16* __restrict__ Aexp)
{
    const int idx = blockIdx.x * blockDim.x + threadIdx.x;     // pairs
    if (idx >= M_TOT * DD / 2) return;
    const int m = idx / (DD / 2), kp = idx % (DD / 2);
    const int k = kp * 2;
    const float2 v = *reinterpret_cast<const float2*>(&x[(size_t)m * DD + k]);
    __nv_bfloat16 h0, l0, h1, l1;
    split_bf16(v.x, h0, l0);
    split_bf16(v.y, h1, l1);
    __nv_bfloat162 hp, lp;
    hp.x = h0; hp.y = h1; lp.x = l0; lp.y = l1;
    const size_t base = (size_t)m * KC1 + k;
    *reinterpret_cast<__nv_bfloat162*>(&Aexp[base])            = hp;
    *reinterpret_cast<__nv_bfloat162*>(&Aexp[base + DD])       = lp;
    *reinterpret_cast<__nv_bfloat162*>(&Aexp[base + 2 * DD])   = hp;
}

// W (K x N fp32, row-major) -> Bexp (Npad x K3pad bf16, K-major), layout [hi | hi | lo]
__global__ void expand_W_kernel(const float* __restrict__ W, __nv_bfloat16* __restrict__ Bexp,
                                int K, int N, int Npad, int K3pad)
{
    const int idx = blockIdx.x * blockDim.x + threadIdx.x;
    if (idx >= Npad * K3pad) return;
    const int n = idx / K3pad, k3 = idx % K3pad;
    __nv_bfloat16 outv = __float2bfloat16(0.f);
    if (n < N && k3 < 3 * K) {
        const int r = k3 / K, k = k3 - r * K;
        __nv_bfloat16 hi, lo;
        split_bf16(W[(size_t)k * N + n], hi, lo);
        outv = (r < 2) ? hi : lo;
    }
    Bexp[idx] = outv;
}

// ---------------- fold (gather) + normalize + crop/zero-pad ----------------
// 4 channels per thread (c, c+10, c+20, c+30): index math amortized 4x.
__global__ void fold_kernel(const float* __restrict__ h, float* __restrict__ img)
{
    const int idx = blockIdx.x * blockDim.x + threadIdx.x;
    if (idx >= BPF * (CCH / 4) * IMGPIX) return;
    const int pix = idx % IMGPIX;
    const int rest = idx / IMGPIX;
    const int cg  = rest % (CCH / 4);    // 0..9
    const int bp  = rest / (CCH / 4);
    const int pi  = pix / WP;
    const int pj  = pix % WP;

    float out[4] = {0.f, 0.f, 0.f, 0.f};
    if (pi >= PAD && pi < PAD + HH && pj >= PAD && pj < PAD + WWID) {
        const int oi_lo = max(0, (pi - 4) / 3);
        const int oi_hi = min(OHN - 1, pi / 3);
        const int oj_lo = max(0, (pj - 4) / 3);
        const int oj_hi = min(OWN - 1, pj / 3);
        float sum[4] = {0.f, 0.f, 0.f, 0.f};
        for (int oi = oi_lo; oi <= oi_hi; ++oi) {
            const int ki = pi - 3 * oi;
            for (int oj = oj_lo; oj <= oj_hi; ++oj) {
                const int kj = pj - 3 * oj;
                const size_t base = (size_t)(bp * LLP + oi * OWN + oj) * HDIM
                                  + cg * KTAPS + ki * KH + kj;
#pragma unroll
                for (int t = 0; t < 4; t++)
                    sum[t] += h[base + t * (10 * KTAPS)];
            }
        }
        const float inv = 1.f / (float)((oi_hi - oi_lo + 1) * (oj_hi - oj_lo + 1));
#pragma unroll
        for (int t = 0; t < 4; t++) out[t] = sum[t] * inv;
    }
#pragma unroll
    for (int t = 0; t < 4; t++)
        img[(size_t)(bp * CCH + cg + 10 * t) * IMGPIX + pix] = out[t];
}

// ---------------- unfold + exact GELU + bf16-split expansion (paired) ----------------
// Writes Aexp (M_TOT x 5888), layout [hi(0:1960) | lo | hi | zeros(5880:5888)]
__global__ void unfold_gelu_expand_kernel(const float* __restrict__ img,
                                          __nv_bfloat16* __restrict__ Aexp)
{
    const int idx = blockIdx.x * blockDim.x + threadIdx.x;     // pairs over HDIM
    if (idx >= M_TOT * (HDIM / 2)) return;
    const int jp    = idx % (HDIM / 2);
    const int token = idx / (HDIM / 2);
    const int j  = jp * 2;
    const int bp = token / LLP;
    const int l  = token % LLP;
    const int oi = l / OWN, oj = l % OWN;
    const int base_pix = (oi * 3) * WP + (oj * 3);

    float ge[2];
#pragma unroll
    for (int u = 0; u < 2; u++) {
        const int jj = j + u;
        const int c  = jj / KTAPS;
        const int k  = jj % KTAPS;
        const int ki = k / KH, kj = k % KH;
        const float v = img[(size_t)(bp * CCH + c) * IMGPIX + base_pix + ki * WP + kj];
        ge[u] = 0.5f * v * (1.f + erff(v * 0.7071067811865475f));
    }
    __nv_bfloat16 h0, l0, h1, l1;
    split_bf16(ge[0], h0, l0);
    split_bf16(ge[1], h1, l1);
    __nv_bfloat162 hp, lp;
    hp.x = h0; hp.y = h1; lp.x = l0; lp.y = l1;
    const size_t base = (size_t)token * KC2 + j;
    *reinterpret_cast<__nv_bfloat162*>(&Aexp[base])             = hp;
    *reinterpret_cast<__nv_bfloat162*>(&Aexp[base + HDIM])      = lp;
    *reinterpret_cast<__nv_bfloat162*>(&Aexp[base + 2 * HDIM])  = hp;
    if (j < KC2 - 3 * HDIM) {               // zero the 8 K-padding cols (threads j=0,2,4,6)
        __nv_bfloat162 z;
        z.x = __float2bfloat16(0.f); z.y = z.x;
        *reinterpret_cast<__nv_bfloat162*>(&Aexp[(size_t)token * KC2 + 3 * HDIM + j]) = z;
    }
}

// ---------------- launch ----------------
extern "C" void kernel_launch(void* const* d_in, const int* in_sizes, int n_in,
                              void* d_out, int out_size)
{
    const float* x  = (const float*)d_in[0];   // (2, 5760, 512)
    const float* W1 = (const float*)d_in[1];   // (512, 1960)
    const float* b1 = (const float*)d_in[2];   // (1960,)
    const float* W2 = (const float*)d_in[3];   // (1960, 512)
    const float* b2 = (const float*)d_in[4];   // (512,)
    float* out = (float*)d_out;                // (2, 5760, 512)

    __nv_bfloat16 *Aexp, *Bexp;
    float *h_ptr, *img_ptr;
    cudaGetSymbolAddress((void**)&Aexp,    g_Aexp);
    cudaGetSymbolAddress((void**)&Bexp,    g_Bexp);
    cudaGetSymbolAddress((void**)&h_ptr,   g_h);
    cudaGetSymbolAddress((void**)&img_ptr, g_img);

    static bool attr_set = false;
    if (!attr_set) {
        cudaFuncSetAttribute(hmma_gemm, cudaFuncAttributeMaxDynamicSharedMemorySize, GEMM_SMEM);
        attr_set = true;
    }

    // --- GEMM1: h = x @ W1 + b1  (3x bf16 split on tensor cores) ---
    {
        int n = M_TOT * DD / 2;
        expand_x_kernel<<<(n + 255) / 256, 256>>>(x, Aexp);
        int nb = NPAD1 * KC1;
        expand_W_kernel<<<(nb + 255) / 256, 256>>>(W1, Bexp, DD, HDIM, NPAD1, KC1);
        dim3 grid(NPAD1 / 128, M_TOT / 128);   // (16, 90)
        hmma_gemm<<<grid, 256, GEMM_SMEM>>>(Aexp, Bexp, b1, h_ptr, KC1, HDIM);
    }
    // --- fold + normalize (4 channels/thread) ---
    {
        const int total = BPF * (CCH / 4) * IMGPIX;
        fold_kernel<<<(total + 255) / 256, 256>>>(h_ptr, img_ptr);
    }
    // --- unfold + gelu + expansion (Aexp reused) ---
    {
        const int total = M_TOT * (HDIM / 2);
        unfold_gelu_expand_kernel<<<(total + 255) / 256, 256>>>(img_ptr, Aexp);
        int nb = NPAD2 * KC2;
        expand_W_kernel<<<(nb + 255) / 256, 256>>>(W2, Bexp, HDIM, DD, NPAD2, KC2);
    }
    // --- GEMM2: out = g @ W2 + b2 ---
    {
        dim3 grid(NPAD2 / 128, M_TOT / 128);   // (4, 90)
        hmma_gemm<<<grid, 256, GEMM_SMEM>>>(Aexp, Bexp, b2, out, KC2, DD);
    }
}